// round 1
// baseline (speedup 1.0000x reference)
#include <cuda_runtime.h>
#include <cuda_bf16.h>
#include <mma.h>
#include <math.h>

using namespace nvcuda;

// Problem capacities (padded to GEMM tile multiples)
#define E_CAP 100096   // multiple of 64
#define N_CAP 10240
#define C 128

// Scratch (device globals: allocation rules forbid cudaMalloc)
__device__ float g_H[(size_t)E_CAP * 64];          // hidden after 3 MLP layers
__device__ float g_MIX[(size_t)E_CAP * 640];       // h @ w3 / 8
__device__ int   g_deg[N_CAP];
__device__ int   g_off[N_CAP + 1];
__device__ int   g_cur[N_CAP];
__device__ int   g_ord[E_CAP];

__device__ __forceinline__ float silu(float x) {
    return x / (1.0f + expf(-x));
}

// ---------------------------------------------------------------------------
// Kernel 1: radial MLP (3 layers, 64-wide) -> g_H
// 256 threads = 4 edges x 64 threads
// ---------------------------------------------------------------------------
__global__ void mlp_kernel(const float* __restrict__ re,
                           const float* __restrict__ w0,
                           const float* __restrict__ w1,
                           const float* __restrict__ w2,
                           int E) {
    __shared__ float s_w0[8 * 64];
    __shared__ float s_w1[64 * 64];
    __shared__ float s_w2[64 * 64];
    __shared__ float hA[4][64];
    __shared__ float hB[4][64];

    int tid = threadIdx.x;
    for (int i = tid; i < 8 * 64; i += 256)  s_w0[i] = w0[i];
    for (int i = tid; i < 64 * 64; i += 256) s_w1[i] = w1[i];
    for (int i = tid; i < 64 * 64; i += 256) s_w2[i] = w2[i];

    int sub = tid >> 6;
    int j   = tid & 63;
    int e   = blockIdx.x * 4 + sub;

    float r[8];
    if (e < E) {
        #pragma unroll
        for (int k = 0; k < 8; k++) r[k] = re[(size_t)e * 8 + k];
    } else {
        #pragma unroll
        for (int k = 0; k < 8; k++) r[k] = 0.f;
    }
    __syncthreads();

    // layer 0
    float acc = 0.f;
    #pragma unroll
    for (int k = 0; k < 8; k++) acc += r[k] * s_w0[k * 64 + j];
    hA[sub][j] = silu(acc * 0.35355339059f);   // 1/sqrt(8)
    __syncthreads();

    // layer 1
    acc = 0.f;
    #pragma unroll 8
    for (int k = 0; k < 64; k++) acc += hA[sub][k] * s_w1[k * 64 + j];
    hB[sub][j] = silu(acc * 0.125f);           // 1/sqrt(64)
    __syncthreads();

    // layer 2
    acc = 0.f;
    #pragma unroll 8
    for (int k = 0; k < 64; k++) acc += hB[sub][k] * s_w2[k * 64 + j];
    float h = silu(acc * 0.125f);

    if (e < E) g_H[(size_t)e * 64 + j] = h;
}

// ---------------------------------------------------------------------------
// Kernel 2: MIX = (H @ w3) / 8   via tf32 wmma (m16n16k8)
// block = 128 threads (4 warps), block tile 64(M) x 64(N), K = 64 full
// ---------------------------------------------------------------------------
__global__ void gemm_mix_kernel(const float* __restrict__ w3, int E) {
    __shared__ float sA[64 * 72];
    __shared__ float sB[64 * 72];

    int warp = threadIdx.x >> 5;
    int m0 = blockIdx.x * 64;
    int n0 = blockIdx.y * 64;

    // load A tile: 64 rows x 64 cols of g_H (row-major, full K)
    for (int i = threadIdx.x; i < 64 * 16; i += 128) {
        int r = i >> 4, q = i & 15;
        float4 v = *(const float4*)(g_H + (size_t)(m0 + r) * 64 + q * 4);
        *(float4*)(sA + r * 72 + q * 4) = v;
    }
    // load B tile: w3[k][n0+j], k=0..63, j=0..63
    for (int i = threadIdx.x; i < 64 * 16; i += 128) {
        int k = i >> 4, q = i & 15;
        *(float4*)(sB + k * 72 + q * 4) =
            *(const float4*)(w3 + (size_t)k * 640 + n0 + q * 4);
    }
    __syncthreads();

    wmma::fragment<wmma::accumulator, 16, 16, 8, float> acc[4];
    #pragma unroll
    for (int j = 0; j < 4; j++) wmma::fill_fragment(acc[j], 0.0f);

    #pragma unroll
    for (int k0 = 0; k0 < 64; k0 += 8) {
        wmma::fragment<wmma::matrix_a, 16, 16, 8, wmma::precision::tf32, wmma::row_major> a;
        wmma::load_matrix_sync(a, sA + (warp * 16) * 72 + k0, 72);
        #pragma unroll
        for (int t = 0; t < a.num_elements; t++) a.x[t] = wmma::__float_to_tf32(a.x[t]);
        #pragma unroll
        for (int j = 0; j < 4; j++) {
            wmma::fragment<wmma::matrix_b, 16, 16, 8, wmma::precision::tf32, wmma::row_major> b;
            wmma::load_matrix_sync(b, sB + k0 * 72 + j * 16, 72);
            #pragma unroll
            for (int t = 0; t < b.num_elements; t++) b.x[t] = wmma::__float_to_tf32(b.x[t]);
            wmma::mma_sync(acc[j], a, b, acc[j]);
        }
    }

    #pragma unroll
    for (int j = 0; j < 4; j++) {
        #pragma unroll
        for (int t = 0; t < acc[j].num_elements; t++) acc[j].x[t] *= 0.125f;
        wmma::store_matrix_sync(g_MIX + (size_t)(m0 + warp * 16) * 640 + n0 + j * 16,
                                acc[j], 640, wmma::mem_row_major);
    }
}

// ---------------------------------------------------------------------------
// CSR-by-receiver build
// ---------------------------------------------------------------------------
__global__ void zero_deg_kernel(int N) {
    int i = blockIdx.x * blockDim.x + threadIdx.x;
    if (i < N) g_deg[i] = 0;
}

__global__ void hist_kernel(const int* __restrict__ recv, int E) {
    int i = blockIdx.x * blockDim.x + threadIdx.x;
    if (i < E) atomicAdd(&g_deg[recv[i]], 1);
}

__global__ void scan_kernel(int N, int E) {
    __shared__ int s[1024];
    int t = threadIdx.x;
    int chunk = (N + 1023) / 1024;
    int lo = t * chunk;
    int hi = min(lo + chunk, N);

    int sum = 0;
    for (int i = lo; i < hi; i++) sum += g_deg[i];
    s[t] = sum;
    __syncthreads();

    // Hillis-Steele inclusive scan over 1024 partials
    for (int d = 1; d < 1024; d <<= 1) {
        int v = (t >= d) ? s[t - d] : 0;
        __syncthreads();
        s[t] += v;
        __syncthreads();
    }

    int run = (t == 0) ? 0 : s[t - 1];
    for (int i = lo; i < hi; i++) {
        g_off[i] = run;
        g_cur[i] = run;
        run += g_deg[i];
    }
    if (t == 0) g_off[N] = E;
}

__global__ void scatter_kernel(const int* __restrict__ recv, int E) {
    int i = blockIdx.x * blockDim.x + threadIdx.x;
    if (i < E) {
        int p = atomicAdd(&g_cur[recv[i]], 1);
        g_ord[p] = i;
    }
}

// ---------------------------------------------------------------------------
// Kernel 6: gather-reduce. block = node, thread = channel c (0..127).
// Accumulates all 11 output values per (node, channel) in registers.
// Uses simplified CG products: CG110*SH_L1=1, CG011*SH_L1=1, CG121*SH_L2=sqrt(3)
// ---------------------------------------------------------------------------
__global__ void gather_kernel(const float* __restrict__ vectors,
                              const float* __restrict__ nf,
                              const int* __restrict__ senders,
                              float* __restrict__ out) {
    int n = blockIdx.x;
    int c = threadIdx.x;
    int lo = g_off[n];
    int hi = g_off[n + 1];

    float as0 = 0.f, as1 = 0.f;
    float a0x = 0.f, a0y = 0.f, a0z = 0.f;   // vs part
    float a1x = 0.f, a1y = 0.f, a1z = 0.f;   // tp1 part
    float a2x = 0.f, a2y = 0.f, a2z = 0.f;   // tp2 part

    const float SQ3 = 1.73205080757f;

    for (int k = lo; k < hi; k++) {
        int e = g_ord[k];
        int s = senders[e];

        float vx = vectors[3 * (size_t)e + 0];
        float vy = vectors[3 * (size_t)e + 1];
        float vz = vectors[3 * (size_t)e + 2];
        float inv = rsqrtf(vx * vx + vy * vy + vz * vz);
        float rx = vx * inv, ry = vy * inv, rz = vz * inv;

        const float* nfr = nf + (size_t)s * 512;
        float ss = nfr[c];
        float v0 = nfr[128 + 3 * c + 0];
        float v1 = nfr[128 + 3 * c + 1];
        float v2 = nfr[128 + 3 * c + 2];

        const float* mix = g_MIX + (size_t)e * 640;
        float m0 = mix[c];
        float m1 = mix[128 + c];
        float m2 = mix[256 + c];
        float m3 = mix[384 + c];
        float m4 = mix[512 + c];

        float dot = v0 * rx + v1 * ry + v2 * rz;   // r_hat . vs

        as0 += ss * m0;         // ss part
        as1 += dot * m1;        // tp0 = vs . r_hat

        a0x += v0 * m2; a0y += v1 * m2; a0z += v2 * m2;          // vs
        a1x += ss * rx * m3; a1y += ss * ry * m3; a1z += ss * rz * m3;  // tp1

        float t2x = SQ3 * (rx * dot - v0 * (1.0f / 3.0f));
        float t2y = SQ3 * (ry * dot - v1 * (1.0f / 3.0f));
        float t2z = SQ3 * (rz * dot - v2 * (1.0f / 3.0f));
        a2x += t2x * m4; a2y += t2y * m4; a2z += t2z * m4;       // tp2
    }

    const float sc = 0.316227766017f;  // 1/sqrt(10)
    size_t base = (size_t)n * 1408;
    out[base + c]        = as0 * sc;
    out[base + 128 + c]  = as1 * sc;
    size_t vb = base + 256;
    out[vb + 3 * (size_t)c + 0] = a0x * sc;
    out[vb + 3 * (size_t)c + 1] = a0y * sc;
    out[vb + 3 * (size_t)c + 2] = a0z * sc;
    out[vb + 3 * (size_t)(128 + c) + 0] = a1x * sc;
    out[vb + 3 * (size_t)(128 + c) + 1] = a1y * sc;
    out[vb + 3 * (size_t)(128 + c) + 2] = a1z * sc;
    out[vb + 3 * (size_t)(256 + c) + 0] = a2x * sc;
    out[vb + 3 * (size_t)(256 + c) + 1] = a2y * sc;
    out[vb + 3 * (size_t)(256 + c) + 2] = a2z * sc;
}

// ---------------------------------------------------------------------------
extern "C" void kernel_launch(void* const* d_in, const int* in_sizes, int n_in,
                              void* d_out, int out_size) {
    const float* vectors   = (const float*)d_in[0];
    const float* node_feat = (const float*)d_in[1];
    const float* radial    = (const float*)d_in[2];
    const float* w0        = (const float*)d_in[3];
    const float* w1        = (const float*)d_in[4];
    const float* w2        = (const float*)d_in[5];
    const float* w3        = (const float*)d_in[6];
    const int*   senders   = (const int*)d_in[7];
    const int*   receivers = (const int*)d_in[8];
    float* out = (float*)d_out;

    int E = in_sizes[0] / 3;
    int N = in_sizes[1] / 512;

    mlp_kernel<<<(E + 3) / 4, 256>>>(radial, w0, w1, w2, E);

    dim3 ggrid((E + 63) / 64, 10);
    gemm_mix_kernel<<<ggrid, 128>>>(w3, E);

    zero_deg_kernel<<<(N + 255) / 256, 256>>>(N);
    hist_kernel<<<(E + 255) / 256, 256>>>(receivers, E);
    scan_kernel<<<1, 1024>>>(N, E);
    scatter_kernel<<<(E + 255) / 256, 256>>>(receivers, E);

    gather_kernel<<<N, 128>>>(vectors, node_feat, senders, out);
}

// round 2
// speedup vs baseline: 1.0919x; 1.0919x over previous
#include <cuda_runtime.h>
#include <cuda_bf16.h>
#include <mma.h>
#include <math.h>

using namespace nvcuda;

#define E_CAP 100096
#define N_CAP 10240
#define C 128
#define M_TILE 128

// Scratch (device globals: allocation rules forbid cudaMalloc)
__device__ float g_MIX[(size_t)E_CAP * 640];
__device__ int   g_deg[N_CAP];
__device__ int   g_off[N_CAP + 1];
__device__ int   g_cur[N_CAP];
__device__ int   g_ord[E_CAP];

__device__ __forceinline__ float silu(float x) {
    return x / (1.0f + expf(-x));
}

// ---------------------------------------------------------------------------
// Fused kernel: radial MLP (3 layers, 64-wide) -> H tile in smem,
// then MIX = (H @ w3)/8 via tf32 wmma over all 10 N-tiles (A tile reused).
// Block = 256 threads, 128 edges.
// ---------------------------------------------------------------------------
__global__ __launch_bounds__(256) void mlp_gemm_kernel(
        const float* __restrict__ re,
        const float* __restrict__ w0,
        const float* __restrict__ w1,
        const float* __restrict__ w2,
        const float* __restrict__ w3,
        int E) {
    extern __shared__ float smem[];
    float* s_w0 = smem;              // 512
    float* s_w1 = s_w0 + 512;        // 4096
    float* s_w2 = s_w1 + 4096;       // 4096
    float* hA   = s_w2 + 4096;       // 256
    float* hB   = hA + 256;          // 256
    float* sA   = hB + 256;          // 128*72 = 9216
    float* sB   = sA + 9216;         // 64*72  = 4608

    int tid = threadIdx.x;
    int m0 = blockIdx.x * M_TILE;

    for (int i = tid; i < 512; i += 256) s_w0[i] = w0[i];
    for (int i = tid; i < 4096; i += 256) { s_w1[i] = w1[i]; s_w2[i] = w2[i]; }
    __syncthreads();

    // ---------------- MLP phase: 32 passes x 4 edges ----------------
    int sub = tid >> 6;      // 0..3
    int j   = tid & 63;      // 0..63

    for (int p = 0; p < 32; p++) {
        int row = p * 4 + sub;
        int e = m0 + row;

        float r[8];
        if (e < E) {
            float4 a = *(const float4*)(re + (size_t)e * 8);
            float4 b = *(const float4*)(re + (size_t)e * 8 + 4);
            r[0]=a.x; r[1]=a.y; r[2]=a.z; r[3]=a.w;
            r[4]=b.x; r[5]=b.y; r[6]=b.z; r[7]=b.w;
        } else {
            #pragma unroll
            for (int k = 0; k < 8; k++) r[k] = 0.f;
        }

        float acc = 0.f;
        #pragma unroll
        for (int k = 0; k < 8; k++) acc += r[k] * s_w0[k * 64 + j];
        hA[sub * 64 + j] = silu(acc * 0.35355339059f);   // 1/sqrt(8)
        __syncthreads();

        acc = 0.f;
        #pragma unroll 8
        for (int k = 0; k < 64; k++) acc += hA[sub * 64 + k] * s_w1[k * 64 + j];
        hB[sub * 64 + j] = silu(acc * 0.125f);           // 1/sqrt(64)
        __syncthreads();

        acc = 0.f;
        #pragma unroll 8
        for (int k = 0; k < 64; k++) acc += hB[sub * 64 + k] * s_w2[k * 64 + j];
        sA[row * 72 + j] = (e < E) ? silu(acc * 0.125f) : 0.f;
        __syncthreads();
    }

    // ---------------- GEMM phase: 8 warps, tile 128(M) x 64(N) ----------------
    int warp = tid >> 5;
    int mrow = warp * 16;

    for (int nt = 0; nt < 10; nt++) {
        // load B tile 64x64 from w3
        for (int i = tid; i < 1024; i += 256) {
            int k = i >> 4, q = i & 15;
            *(float4*)(sB + k * 72 + q * 4) =
                *(const float4*)(w3 + (size_t)k * 640 + nt * 64 + q * 4);
        }
        __syncthreads();

        wmma::fragment<wmma::accumulator, 16, 16, 8, float> acc[4];
        #pragma unroll
        for (int jj = 0; jj < 4; jj++) wmma::fill_fragment(acc[jj], 0.0f);

        #pragma unroll
        for (int k0 = 0; k0 < 64; k0 += 8) {
            wmma::fragment<wmma::matrix_a, 16, 16, 8, wmma::precision::tf32, wmma::row_major> a;
            wmma::load_matrix_sync(a, sA + mrow * 72 + k0, 72);
            #pragma unroll
            for (int t = 0; t < a.num_elements; t++) a.x[t] = wmma::__float_to_tf32(a.x[t]);
            #pragma unroll
            for (int jj = 0; jj < 4; jj++) {
                wmma::fragment<wmma::matrix_b, 16, 16, 8, wmma::precision::tf32, wmma::row_major> b;
                wmma::load_matrix_sync(b, sB + k0 * 72 + jj * 16, 72);
                #pragma unroll
                for (int t = 0; t < b.num_elements; t++) b.x[t] = wmma::__float_to_tf32(b.x[t]);
                wmma::mma_sync(acc[jj], a, b, acc[jj]);
            }
        }

        #pragma unroll
        for (int jj = 0; jj < 4; jj++) {
            #pragma unroll
            for (int t = 0; t < acc[jj].num_elements; t++) acc[jj].x[t] *= 0.125f;
            wmma::store_matrix_sync(g_MIX + (size_t)(m0 + mrow) * 640 + nt * 64 + jj * 16,
                                    acc[jj], 640, wmma::mem_row_major);
        }
        __syncthreads();
    }
}

// ---------------------------------------------------------------------------
// CSR-by-receiver build
// ---------------------------------------------------------------------------
__global__ void zero_deg_kernel(int N) {
    int i = blockIdx.x * blockDim.x + threadIdx.x;
    if (i < N) g_deg[i] = 0;
}

__global__ void hist_kernel(const int* __restrict__ recv, int E) {
    int i = blockIdx.x * blockDim.x + threadIdx.x;
    if (i < E) atomicAdd(&g_deg[recv[i]], 1);
}

__global__ void scan_kernel(int N, int E) {
    __shared__ int s[1024];
    int t = threadIdx.x;
    int chunk = (N + 1023) / 1024;
    int lo = t * chunk;
    int hi = min(lo + chunk, N);

    int sum = 0;
    for (int i = lo; i < hi; i++) sum += g_deg[i];
    s[t] = sum;
    __syncthreads();

    for (int d = 1; d < 1024; d <<= 1) {
        int v = (t >= d) ? s[t - d] : 0;
        __syncthreads();
        s[t] += v;
        __syncthreads();
    }

    int run = (t == 0) ? 0 : s[t - 1];
    for (int i = lo; i < hi; i++) {
        g_off[i] = run;
        g_cur[i] = run;
        run += g_deg[i];
    }
    if (t == 0) g_off[N] = E;
}

__global__ void scatter_kernel(const int* __restrict__ recv, int E) {
    int i = blockIdx.x * blockDim.x + threadIdx.x;
    if (i < E) {
        int p = atomicAdd(&g_cur[recv[i]], 1);
        g_ord[p] = i;
    }
}

// ---------------------------------------------------------------------------
// Gather-reduce. block = node, thread = channel c (0..127).
// Simplified CG products: CG110*SH_L1=1, CG011*SH_L1=1, CG121*SH_L2=sqrt(3)
// ---------------------------------------------------------------------------
__global__ void gather_kernel(const float* __restrict__ vectors,
                              const float* __restrict__ nf,
                              const int* __restrict__ senders,
                              float* __restrict__ out) {
    int n = blockIdx.x;
    int c = threadIdx.x;
    int lo = g_off[n];
    int hi = g_off[n + 1];

    float as0 = 0.f, as1 = 0.f;
    float a0x = 0.f, a0y = 0.f, a0z = 0.f;
    float a1x = 0.f, a1y = 0.f, a1z = 0.f;
    float a2x = 0.f, a2y = 0.f, a2z = 0.f;

    const float SQ3 = 1.73205080757f;

    for (int k = lo; k < hi; k++) {
        int e = g_ord[k];
        int s = senders[e];

        float vx = vectors[3 * (size_t)e + 0];
        float vy = vectors[3 * (size_t)e + 1];
        float vz = vectors[3 * (size_t)e + 2];
        float inv = rsqrtf(vx * vx + vy * vy + vz * vz);
        float rx = vx * inv, ry = vy * inv, rz = vz * inv;

        const float* nfr = nf + (size_t)s * 512;
        float ss = nfr[c];
        float v0 = nfr[128 + 3 * c + 0];
        float v1 = nfr[128 + 3 * c + 1];
        float v2 = nfr[128 + 3 * c + 2];

        const float* mix = g_MIX + (size_t)e * 640;
        float m0 = mix[c];
        float m1 = mix[128 + c];
        float m2 = mix[256 + c];
        float m3 = mix[384 + c];
        float m4 = mix[512 + c];

        float dot = v0 * rx + v1 * ry + v2 * rz;

        as0 += ss * m0;
        as1 += dot * m1;

        a0x += v0 * m2; a0y += v1 * m2; a0z += v2 * m2;
        a1x += ss * rx * m3; a1y += ss * ry * m3; a1z += ss * rz * m3;

        float t2x = SQ3 * (rx * dot - v0 * (1.0f / 3.0f));
        float t2y = SQ3 * (ry * dot - v1 * (1.0f / 3.0f));
        float t2z = SQ3 * (rz * dot - v2 * (1.0f / 3.0f));
        a2x += t2x * m4; a2y += t2y * m4; a2z += t2z * m4;
    }

    const float sc = 0.316227766017f;  // 1/sqrt(10)
    size_t base = (size_t)n * 1408;
    out[base + c]        = as0 * sc;
    out[base + 128 + c]  = as1 * sc;
    size_t vb = base + 256;
    out[vb + 3 * (size_t)c + 0] = a0x * sc;
    out[vb + 3 * (size_t)c + 1] = a0y * sc;
    out[vb + 3 * (size_t)c + 2] = a0z * sc;
    out[vb + 3 * (size_t)(128 + c) + 0] = a1x * sc;
    out[vb + 3 * (size_t)(128 + c) + 1] = a1y * sc;
    out[vb + 3 * (size_t)(128 + c) + 2] = a1z * sc;
    out[vb + 3 * (size_t)(256 + c) + 0] = a2x * sc;
    out[vb + 3 * (size_t)(256 + c) + 1] = a2y * sc;
    out[vb + 3 * (size_t)(256 + c) + 2] = a2z * sc;
}

// ---------------------------------------------------------------------------
extern "C" void kernel_launch(void* const* d_in, const int* in_sizes, int n_in,
                              void* d_out, int out_size) {
    const float* vectors   = (const float*)d_in[0];
    const float* node_feat = (const float*)d_in[1];
    const float* radial    = (const float*)d_in[2];
    const float* w0        = (const float*)d_in[3];
    const float* w1        = (const float*)d_in[4];
    const float* w2        = (const float*)d_in[5];
    const float* w3        = (const float*)d_in[6];
    const int*   senders   = (const int*)d_in[7];
    const int*   receivers = (const int*)d_in[8];
    float* out = (float*)d_out;

    int E = in_sizes[0] / 3;
    int N = in_sizes[1] / 512;

    const int SMEM_BYTES = (512 + 4096 + 4096 + 256 + 256 + 9216 + 4608) * 4; // 92160
    cudaFuncSetAttribute(mlp_gemm_kernel,
                         cudaFuncAttributeMaxDynamicSharedMemorySize, SMEM_BYTES);

    mlp_gemm_kernel<<<(E + M_TILE - 1) / M_TILE, 256, SMEM_BYTES>>>(
        radial, w0, w1, w2, w3, E);

    zero_deg_kernel<<<(N + 255) / 256, 256>>>(N);
    hist_kernel<<<(E + 255) / 256, 256>>>(receivers, E);
    scan_kernel<<<1, 1024>>>(N, E);
    scatter_kernel<<<(E + 255) / 256, 256>>>(receivers, E);

    gather_kernel<<<N, 128>>>(vectors, node_feat, senders, out);
}

// round 3
// speedup vs baseline: 1.1522x; 1.0552x over previous
#include <cuda_runtime.h>
#include <cuda_fp16.h>
#include <mma.h>
#include <math.h>

using namespace nvcuda;

#define E_CAP 100096
#define N_CAP 10240
#define C 128
#define M_TILE 128

// Scratch (device globals: allocation rules forbid cudaMalloc)
__device__ __half g_MIX[(size_t)E_CAP * 640];
__device__ int   g_deg[N_CAP];
__device__ int   g_off[N_CAP + 1];
__device__ int   g_cur[N_CAP];
__device__ int   g_ord[E_CAP];

__device__ __forceinline__ float silu(float x) {
    return x / (1.0f + expf(-x));
}

// ---------------------------------------------------------------------------
// Fully tensor-core fused kernel:
//   h1 = silu(RE@W0/sqrt8); h2 = silu(h1@W1/8); h3 = silu(h2@W2/8);
//   MIX = h3@W3/8  (fp16 output)
// Block = 256 threads (8 warps), tile = 128 edges. Each warp owns 16 rows,
// so the layer GEMMs run in-place in one smem buffer with no block syncs.
// ---------------------------------------------------------------------------
__global__ __launch_bounds__(256) void mlp_gemm_kernel(
        const float* __restrict__ re,
        const float* __restrict__ w0,
        const float* __restrict__ w1,
        const float* __restrict__ w2,
        const float* __restrict__ w3,
        int E) {
    extern __shared__ float smem[];
    float* sW0 = smem;               // 8  x 72 = 576
    float* sW1 = sW0 + 576;          // 64 x 72 = 4608
    float* sW2 = sW1 + 4608;         // 64 x 72 = 4608
    float* sH  = sW2 + 4608;         // 128x 72 = 9216
    float* sB  = sH + 9216;          // 64 x 72 = 4608
    float* stg = sB + 4608;          // 8 warps x 16 x 68 = 8704

    int tid = threadIdx.x;
    int warp = tid >> 5;
    int lane = tid & 31;
    int m0 = blockIdx.x * M_TILE;
    int mrow = warp * 16;
    float* mystg = stg + warp * (16 * 68);

    // load weights (once per block)
    for (int i = tid; i < 512; i += 256)  sW0[(i >> 6) * 72 + (i & 63)] = w0[i];
    for (int i = tid; i < 4096; i += 256) {
        int r = i >> 6, c = i & 63;
        sW1[r * 72 + c] = w1[i];
        sW2[r * 72 + c] = w2[i];
    }
    // load RE tile into sH cols 0..7 (zero-pad rows >= E)
    for (int i = tid; i < 128 * 8; i += 256) {
        int r = i >> 3, c = i & 7;
        int e = m0 + r;
        sH[r * 72 + c] = (e < E) ? re[(size_t)e * 8 + c] : 0.f;
    }
    __syncthreads();

    typedef wmma::fragment<wmma::matrix_a, 16, 16, 8, wmma::precision::tf32, wmma::row_major> AFrag;
    typedef wmma::fragment<wmma::matrix_b, 16, 16, 8, wmma::precision::tf32, wmma::row_major> BFrag;
    typedef wmma::fragment<wmma::accumulator, 16, 16, 8, float> CFrag;

    CFrag acc[4];

    // ---------- layer 0: [16x8] @ [8x64] ----------
    {
        #pragma unroll
        for (int jj = 0; jj < 4; jj++) wmma::fill_fragment(acc[jj], 0.0f);
        AFrag a;
        wmma::load_matrix_sync(a, sH + mrow * 72, 72);
        #pragma unroll
        for (int t = 0; t < a.num_elements; t++) a.x[t] = wmma::__float_to_tf32(a.x[t]);
        #pragma unroll
        for (int jj = 0; jj < 4; jj++) {
            BFrag b;
            wmma::load_matrix_sync(b, sW0 + jj * 16, 72);
            #pragma unroll
            for (int t = 0; t < b.num_elements; t++) b.x[t] = wmma::__float_to_tf32(b.x[t]);
            wmma::mma_sync(acc[jj], a, b, acc[jj]);
        }
        #pragma unroll
        for (int jj = 0; jj < 4; jj++) {
            #pragma unroll
            for (int t = 0; t < acc[jj].num_elements; t++)
                acc[jj].x[t] = silu(acc[jj].x[t] * 0.35355339059f);
            wmma::store_matrix_sync(sH + mrow * 72 + jj * 16, acc[jj], 72, wmma::mem_row_major);
        }
        __syncwarp();
    }

    // ---------- layers 1 & 2: [16x64] @ [64x64], in-place per-warp ----------
    for (int layer = 0; layer < 2; layer++) {
        const float* W = (layer == 0) ? sW1 : sW2;
        #pragma unroll
        for (int jj = 0; jj < 4; jj++) wmma::fill_fragment(acc[jj], 0.0f);
        #pragma unroll
        for (int k0 = 0; k0 < 64; k0 += 8) {
            AFrag a;
            wmma::load_matrix_sync(a, sH + mrow * 72 + k0, 72);
            #pragma unroll
            for (int t = 0; t < a.num_elements; t++) a.x[t] = wmma::__float_to_tf32(a.x[t]);
            #pragma unroll
            for (int jj = 0; jj < 4; jj++) {
                BFrag b;
                wmma::load_matrix_sync(b, W + k0 * 72 + jj * 16, 72);
                #pragma unroll
                for (int t = 0; t < b.num_elements; t++) b.x[t] = wmma::__float_to_tf32(b.x[t]);
                wmma::mma_sync(acc[jj], a, b, acc[jj]);
            }
        }
        #pragma unroll
        for (int jj = 0; jj < 4; jj++) {
            #pragma unroll
            for (int t = 0; t < acc[jj].num_elements; t++)
                acc[jj].x[t] = silu(acc[jj].x[t] * 0.125f);
            wmma::store_matrix_sync(sH + mrow * 72 + jj * 16, acc[jj], 72, wmma::mem_row_major);
        }
        __syncwarp();
    }

    // ---------- main GEMM: [128x64] @ [64x640] over 10 N-tiles ----------
    for (int nt = 0; nt < 10; nt++) {
        __syncthreads();
        for (int i = tid; i < 1024; i += 256) {
            int k = i >> 4, q = i & 15;
            *(float4*)(sB + k * 72 + q * 4) =
                *(const float4*)(w3 + (size_t)k * 640 + nt * 64 + q * 4);
        }
        __syncthreads();

        #pragma unroll
        for (int jj = 0; jj < 4; jj++) wmma::fill_fragment(acc[jj], 0.0f);
        #pragma unroll
        for (int k0 = 0; k0 < 64; k0 += 8) {
            AFrag a;
            wmma::load_matrix_sync(a, sH + mrow * 72 + k0, 72);
            #pragma unroll
            for (int t = 0; t < a.num_elements; t++) a.x[t] = wmma::__float_to_tf32(a.x[t]);
            #pragma unroll
            for (int jj = 0; jj < 4; jj++) {
                BFrag b;
                wmma::load_matrix_sync(b, sB + k0 * 72 + jj * 16, 72);
                #pragma unroll
                for (int t = 0; t < b.num_elements; t++) b.x[t] = wmma::__float_to_tf32(b.x[t]);
                wmma::mma_sync(acc[jj], a, b, acc[jj]);
            }
        }

        // scale, stage in smem, convert to fp16, write out
        #pragma unroll
        for (int jj = 0; jj < 4; jj++) {
            #pragma unroll
            for (int t = 0; t < acc[jj].num_elements; t++) acc[jj].x[t] *= 0.125f;
            wmma::store_matrix_sync(mystg + jj * 16, acc[jj], 68, wmma::mem_row_major);
        }
        __syncwarp();
        for (int idx = lane; idx < 16 * 64; idx += 32) {
            int r = idx >> 6, c = idx & 63;
            g_MIX[(size_t)(m0 + mrow + r) * 640 + nt * 64 + c] =
                __float2half(mystg[r * 68 + c]);
        }
        __syncwarp();
    }
}

// ---------------------------------------------------------------------------
// CSR-by-receiver build
// ---------------------------------------------------------------------------
__global__ void zero_deg_kernel(int N) {
    int i = blockIdx.x * blockDim.x + threadIdx.x;
    if (i < N) g_deg[i] = 0;
}

__global__ void hist_kernel(const int* __restrict__ recv, int E) {
    int i = blockIdx.x * blockDim.x + threadIdx.x;
    if (i < E) atomicAdd(&g_deg[recv[i]], 1);
}

__global__ void scan_kernel(int N, int E) {
    __shared__ int s[1024];
    int t = threadIdx.x;
    int chunk = (N + 1023) / 1024;
    int lo = t * chunk;
    int hi = min(lo + chunk, N);

    int sum = 0;
    for (int i = lo; i < hi; i++) sum += g_deg[i];
    s[t] = sum;
    __syncthreads();

    for (int d = 1; d < 1024; d <<= 1) {
        int v = (t >= d) ? s[t - d] : 0;
        __syncthreads();
        s[t] += v;
        __syncthreads();
    }

    int run = (t == 0) ? 0 : s[t - 1];
    for (int i = lo; i < hi; i++) {
        g_off[i] = run;
        g_cur[i] = run;
        run += g_deg[i];
    }
    if (t == 0) g_off[N] = E;
}

__global__ void scatter_kernel(const int* __restrict__ recv, int E) {
    int i = blockIdx.x * blockDim.x + threadIdx.x;
    if (i < E) {
        int p = atomicAdd(&g_cur[recv[i]], 1);
        g_ord[p] = i;
    }
}

// ---------------------------------------------------------------------------
// Gather-reduce. block = node, thread = channel c (0..127).
// Simplified CG products: CG110*SH_L1=1, CG011*SH_L1=1, CG121*SH_L2=sqrt(3)
// ---------------------------------------------------------------------------
__global__ void gather_kernel(const float* __restrict__ vectors,
                              const float* __restrict__ nf,
                              const int* __restrict__ senders,
                              float* __restrict__ out) {
    int n = blockIdx.x;
    int c = threadIdx.x;
    int lo = g_off[n];
    int hi = g_off[n + 1];

    float as0 = 0.f, as1 = 0.f;
    float a0x = 0.f, a0y = 0.f, a0z = 0.f;
    float a1x = 0.f, a1y = 0.f, a1z = 0.f;
    float a2x = 0.f, a2y = 0.f, a2z = 0.f;

    const float SQ3 = 1.73205080757f;

    for (int k = lo; k < hi; k++) {
        int e = g_ord[k];
        int s = senders[e];

        float vx = vectors[3 * (size_t)e + 0];
        float vy = vectors[3 * (size_t)e + 1];
        float vz = vectors[3 * (size_t)e + 2];
        float inv = rsqrtf(vx * vx + vy * vy + vz * vz);
        float rx = vx * inv, ry = vy * inv, rz = vz * inv;

        const float* nfr = nf + (size_t)s * 512;
        float ss = nfr[c];
        float v0 = nfr[128 + 3 * c + 0];
        float v1 = nfr[128 + 3 * c + 1];
        float v2 = nfr[128 + 3 * c + 2];

        const __half* mix = g_MIX + (size_t)e * 640;
        float m0 = __half2float(mix[c]);
        float m1 = __half2float(mix[128 + c]);
        float m2 = __half2float(mix[256 + c]);
        float m3 = __half2float(mix[384 + c]);
        float m4 = __half2float(mix[512 + c]);

        float dot = v0 * rx + v1 * ry + v2 * rz;

        as0 += ss * m0;
        as1 += dot * m1;

        a0x += v0 * m2; a0y += v1 * m2; a0z += v2 * m2;
        a1x += ss * rx * m3; a1y += ss * ry * m3; a1z += ss * rz * m3;

        float t2x = SQ3 * (rx * dot - v0 * (1.0f / 3.0f));
        float t2y = SQ3 * (ry * dot - v1 * (1.0f / 3.0f));
        float t2z = SQ3 * (rz * dot - v2 * (1.0f / 3.0f));
        a2x += t2x * m4; a2y += t2y * m4; a2z += t2z * m4;
    }

    const float sc = 0.316227766017f;  // 1/sqrt(10)
    size_t base = (size_t)n * 1408;
    out[base + c]        = as0 * sc;
    out[base + 128 + c]  = as1 * sc;
    size_t vb = base + 256;
    out[vb + 3 * (size_t)c + 0] = a0x * sc;
    out[vb + 3 * (size_t)c + 1] = a0y * sc;
    out[vb + 3 * (size_t)c + 2] = a0z * sc;
    out[vb + 3 * (size_t)(128 + c) + 0] = a1x * sc;
    out[vb + 3 * (size_t)(128 + c) + 1] = a1y * sc;
    out[vb + 3 * (size_t)(128 + c) + 2] = a1z * sc;
    out[vb + 3 * (size_t)(256 + c) + 0] = a2x * sc;
    out[vb + 3 * (size_t)(256 + c) + 1] = a2y * sc;
    out[vb + 3 * (size_t)(256 + c) + 2] = a2z * sc;
}

// ---------------------------------------------------------------------------
extern "C" void kernel_launch(void* const* d_in, const int* in_sizes, int n_in,
                              void* d_out, int out_size) {
    const float* vectors   = (const float*)d_in[0];
    const float* node_feat = (const float*)d_in[1];
    const float* radial    = (const float*)d_in[2];
    const float* w0        = (const float*)d_in[3];
    const float* w1        = (const float*)d_in[4];
    const float* w2        = (const float*)d_in[5];
    const float* w3        = (const float*)d_in[6];
    const int*   senders   = (const int*)d_in[7];
    const int*   receivers = (const int*)d_in[8];
    float* out = (float*)d_out;

    int E = in_sizes[0] / 3;
    int N = in_sizes[1] / 512;

    const int SMEM_BYTES = (576 + 4608 + 4608 + 9216 + 4608 + 8704) * 4; // 129280
    cudaFuncSetAttribute(mlp_gemm_kernel,
                         cudaFuncAttributeMaxDynamicSharedMemorySize, SMEM_BYTES);

    mlp_gemm_kernel<<<(E + M_TILE - 1) / M_TILE, 256, SMEM_BYTES>>>(
        radial, w0, w1, w2, w3, E);

    zero_deg_kernel<<<(N + 255) / 256, 256>>>(N);
    hist_kernel<<<(E + 255) / 256, 256>>>(receivers, E);
    scan_kernel<<<1, 1024>>>(N, E);
    scatter_kernel<<<(E + 255) / 256, 256>>>(receivers, E);

    gather_kernel<<<N, 128>>>(vectors, node_feat, senders, out);
}

// round 8
// speedup vs baseline: 1.6902x; 1.4669x over previous
#include <cuda_runtime.h>
#include <cuda_fp16.h>
#include <mma.h>
#include <math.h>

using namespace nvcuda;

#define E_CAP 100096
#define N_CAP 10240
#define C 128
#define M_TILE 128

// Scratch (device globals: allocation rules forbid cudaMalloc)
__device__ __half g_MIX[(size_t)E_CAP * 640];
__device__ __half g_w0h[512];
__device__ __half g_w1h[4096];
__device__ __half g_w2h[4096];
__device__ __half g_w3h[40960];
__device__ int   g_deg[N_CAP];
__device__ int   g_off[N_CAP + 1];
__device__ int   g_cur[N_CAP];
__device__ int   g_ord[E_CAP];
__device__ int   g_snd[E_CAP];

__device__ __forceinline__ float silu(float x) {
    return x / (1.0f + expf(-x));
}

// ---------------------------------------------------------------------------
// Convert weights fp32 -> fp16 (once per call; tiny)
// ---------------------------------------------------------------------------
__global__ void convert_weights_kernel(const float* __restrict__ w0,
                                       const float* __restrict__ w1,
                                       const float* __restrict__ w2,
                                       const float* __restrict__ w3) {
    int i = blockIdx.x * blockDim.x + threadIdx.x;
    if (i < 512)   g_w0h[i] = __float2half(w0[i]);
    if (i < 4096)  { g_w1h[i] = __float2half(w1[i]); g_w2h[i] = __float2half(w2[i]); }
    if (i < 40960) g_w3h[i] = __float2half(w3[i]);
}

// ---------------------------------------------------------------------------
// Fused fp16-tensor-core kernel:
//   h1 = silu(RE@W0/sqrt8); h2 = silu(h1@W1/8); h3 = silu(h2@W2/8);
//   MIX = h3@W3/8  (fp16 out). Block = 256 thr (8 warps), tile = 128 edges.
//   Each warp owns 16 rows -> layer chain is per-warp, no block syncs.
// ---------------------------------------------------------------------------
__global__ __launch_bounds__(256) void mlp_gemm_kernel(
        const float* __restrict__ re, int E) {
    extern __shared__ char smem_raw[];
    __half* sW0 = (__half*)smem_raw;       // 16 x 72 (rows 8..15 zero)
    __half* sW1 = sW0 + 16 * 72;           // 64 x 72
    __half* sW2 = sW1 + 64 * 72;           // 64 x 72
    __half* sH  = sW2 + 64 * 72;           // 128 x 72
    __half* sB  = sH + 128 * 72;           // 64 x 72
    float*  stg = (float*)(sB + 64 * 72);  // 8 warps x 16 x 68 floats
    // halves: 1152+4608+4608+9216+4608 = 24192 -> 48384 B; stg 34816 B; total 83200 B

    int tid = threadIdx.x;
    int warp = tid >> 5;
    int lane = tid & 31;
    int m0 = blockIdx.x * M_TILE;
    int mrow = warp * 16;
    float* mystg = stg + warp * (16 * 68);

    // weights into smem (pad regions zeroed)
    for (int i = tid; i < 16 * 72; i += 256) {
        int r = i / 72, c = i % 72;
        sW0[i] = (r < 8 && c < 64) ? g_w0h[r * 64 + c] : __float2half(0.f);
    }
    for (int i = tid; i < 64 * 72; i += 256) {
        int r = i / 72, c = i % 72;
        __half z = __float2half(0.f);
        sW1[i] = (c < 64) ? g_w1h[r * 64 + c] : z;
        sW2[i] = (c < 64) ? g_w2h[r * 64 + c] : z;
    }
    // RE tile -> sH cols 0..15 (cols 8..15 zero, zero-pad rows >= E)
    for (int i = tid; i < 128 * 16; i += 256) {
        int r = i >> 4, c = i & 15;
        int e = m0 + r;
        float v = (e < E && c < 8) ? re[(size_t)e * 8 + c] : 0.f;
        sH[r * 72 + c] = __float2half(v);
    }
    __syncthreads();

    typedef wmma::fragment<wmma::matrix_a, 16, 16, 16, __half, wmma::row_major> AFrag;
    typedef wmma::fragment<wmma::matrix_b, 16, 16, 16, __half, wmma::row_major> BFrag;
    typedef wmma::fragment<wmma::accumulator, 16, 16, 16, float> CFrag;

    CFrag acc[4];

    // ---------- layer 0: [16x16(pad)] @ [16x64] ----------
    {
        #pragma unroll
        for (int jj = 0; jj < 4; jj++) wmma::fill_fragment(acc[jj], 0.0f);
        AFrag a;
        wmma::load_matrix_sync(a, sH + mrow * 72, 72);
        #pragma unroll
        for (int jj = 0; jj < 4; jj++) {
            BFrag b;
            wmma::load_matrix_sync(b, sW0 + jj * 16, 72);
            wmma::mma_sync(acc[jj], a, b, acc[jj]);
        }
        #pragma unroll
        for (int jj = 0; jj < 4; jj++) {
            #pragma unroll
            for (int t = 0; t < acc[jj].num_elements; t++)
                acc[jj].x[t] = silu(acc[jj].x[t] * 0.35355339059f);
            wmma::store_matrix_sync(mystg + jj * 16, acc[jj], 68, wmma::mem_row_major);
        }
        __syncwarp();
        for (int idx = lane; idx < 16 * 64; idx += 32) {
            int r = idx >> 6, c = idx & 63;
            sH[(mrow + r) * 72 + c] = __float2half(mystg[r * 68 + c]);
        }
        __syncwarp();
    }

    // ---------- layers 1 & 2: [16x64] @ [64x64], per-warp in place ----------
    for (int layer = 0; layer < 2; layer++) {
        const __half* W = (layer == 0) ? sW1 : sW2;
        #pragma unroll
        for (int jj = 0; jj < 4; jj++) wmma::fill_fragment(acc[jj], 0.0f);
        #pragma unroll
        for (int k0 = 0; k0 < 64; k0 += 16) {
            AFrag a;
            wmma::load_matrix_sync(a, sH + mrow * 72 + k0, 72);
            #pragma unroll
            for (int jj = 0; jj < 4; jj++) {
                BFrag b;
                wmma::load_matrix_sync(b, W + k0 * 72 + jj * 16, 72);
                wmma::mma_sync(acc[jj], a, b, acc[jj]);
            }
        }
        #pragma unroll
        for (int jj = 0; jj < 4; jj++) {
            #pragma unroll
            for (int t = 0; t < acc[jj].num_elements; t++)
                acc[jj].x[t] = silu(acc[jj].x[t] * 0.125f);
            wmma::store_matrix_sync(mystg + jj * 16, acc[jj], 68, wmma::mem_row_major);
        }
        __syncwarp();
        for (int idx = lane; idx < 16 * 64; idx += 32) {
            int r = idx >> 6, c = idx & 63;
            sH[(mrow + r) * 72 + c] = __float2half(mystg[r * 68 + c]);
        }
        __syncwarp();
    }

    // ---------- main GEMM: [128x64] @ [64x640], 10 N-tiles ----------
    for (int nt = 0; nt < 10; nt++) {
        __syncthreads();
        // load B tile 64x64 (half) via 128-bit loads
        for (int i = tid; i < 512; i += 256) {
            int k = i >> 3, q = i & 7;       // q: group of 8 halfs
            *(float4*)(sB + k * 72 + q * 8) =
                *(const float4*)(g_w3h + (size_t)k * 640 + nt * 64 + q * 8);
        }
        __syncthreads();

        #pragma unroll
        for (int jj = 0; jj < 4; jj++) wmma::fill_fragment(acc[jj], 0.0f);
        #pragma unroll
        for (int k0 = 0; k0 < 64; k0 += 16) {
            AFrag a;
            wmma::load_matrix_sync(a, sH + mrow * 72 + k0, 72);
            #pragma unroll
            for (int jj = 0; jj < 4; jj++) {
                BFrag b;
                wmma::load_matrix_sync(b, sB + k0 * 72 + jj * 16, 72);
                wmma::mma_sync(acc[jj], a, b, acc[jj]);
            }
        }

        #pragma unroll
        for (int jj = 0; jj < 4; jj++) {
            #pragma unroll
            for (int t = 0; t < acc[jj].num_elements; t++) acc[jj].x[t] *= 0.125f;
            wmma::store_matrix_sync(mystg + jj * 16, acc[jj], 68, wmma::mem_row_major);
        }
        __syncwarp();
        // half2 stores to g_MIX
        for (int idx = lane; idx < 16 * 32; idx += 32) {
            int r = idx >> 5, c2 = idx & 31;
            __half2 h2 = __floats2half2_rn(mystg[r * 68 + c2 * 2],
                                           mystg[r * 68 + c2 * 2 + 1]);
            *(__half2*)(g_MIX + (size_t)(m0 + mrow + r) * 640 + nt * 64 + c2 * 2) = h2;
        }
        __syncwarp();
    }
}

// ---------------------------------------------------------------------------
// CSR-by-receiver build
// ---------------------------------------------------------------------------
__global__ void zero_deg_kernel(int N) {
    int i = blockIdx.x * blockDim.x + threadIdx.x;
    if (i < N) g_deg[i] = 0;
}

__global__ void hist_kernel(const int* __restrict__ recv, int E) {
    int i = blockIdx.x * blockDim.x + threadIdx.x;
    if (i < E) atomicAdd(&g_deg[recv[i]], 1);
}

__global__ void scan_kernel(int N, int E) {
    __shared__ int s[1024];
    int t = threadIdx.x;
    int chunk = (N + 1023) / 1024;
    int lo = t * chunk;
    int hi = min(lo + chunk, N);

    int sum = 0;
    for (int i = lo; i < hi; i++) sum += g_deg[i];
    s[t] = sum;
    __syncthreads();

    for (int d = 1; d < 1024; d <<= 1) {
        int v = (t >= d) ? s[t - d] : 0;
        __syncthreads();
        s[t] += v;
        __syncthreads();
    }

    int run = (t == 0) ? 0 : s[t - 1];
    for (int i = lo; i < hi; i++) {
        g_off[i] = run;
        g_cur[i] = run;
        run += g_deg[i];
    }
    if (t == 0) g_off[N] = E;
}

__global__ void scatter_kernel(const int* __restrict__ recv,
                               const int* __restrict__ send, int E) {
    int i = blockIdx.x * blockDim.x + threadIdx.x;
    if (i < E) {
        int p = atomicAdd(&g_cur[recv[i]], 1);
        g_ord[p] = i;
        g_snd[p] = send[i];
    }
}

// ---------------------------------------------------------------------------
// Gather-reduce. block = node, thread = channel c (0..127).
// Simplified CG products: CG110*SH_L1=1, CG011*SH_L1=1, CG121*SH_L2=sqrt(3)
// ---------------------------------------------------------------------------
__global__ void gather_kernel(const float* __restrict__ vectors,
                              const float* __restrict__ nf,
                              float* __restrict__ out) {
    int n = blockIdx.x;
    int c = threadIdx.x;
    int lo = g_off[n];
    int hi = g_off[n + 1];

    float as0 = 0.f, as1 = 0.f;
    float a0x = 0.f, a0y = 0.f, a0z = 0.f;
    float a1x = 0.f, a1y = 0.f, a1z = 0.f;
    float a2x = 0.f, a2y = 0.f, a2z = 0.f;

    const float SQ3 = 1.73205080757f;

    for (int k = lo; k < hi; k++) {
        int e = g_ord[k];
        int s = g_snd[k];

        float vx = vectors[3 * (size_t)e + 0];
        float vy = vectors[3 * (size_t)e + 1];
        float vz = vectors[3 * (size_t)e + 2];
        float inv = rsqrtf(vx * vx + vy * vy + vz * vz);
        float rx = vx * inv, ry = vy * inv, rz = vz * inv;

        const float* nfr = nf + (size_t)s * 512;
        float ss = nfr[c];
        float v0 = nfr[128 + 3 * c + 0];
        float v1 = nfr[128 + 3 * c + 1];
        float v2 = nfr[128 + 3 * c + 2];

        const __half* mix = g_MIX + (size_t)e * 640;
        float m0 = __half2float(mix[c]);
        float m1 = __half2float(mix[128 + c]);
        float m2 = __half2float(mix[256 + c]);
        float m3 = __half2float(mix[384 + c]);
        float m4 = __half2float(mix[512 + c]);

        float dot = v0 * rx + v1 * ry + v2 * rz;

        as0 += ss * m0;
        as1 += dot * m1;

        a0x += v0 * m2; a0y += v1 * m2; a0z += v2 * m2;
        a1x += ss * rx * m3; a1y += ss * ry * m3; a1z += ss * rz * m3;

        float t2x = SQ3 * (rx * dot - v0 * (1.0f / 3.0f));
        float t2y = SQ3 * (ry * dot - v1 * (1.0f / 3.0f));
        float t2z = SQ3 * (rz * dot - v2 * (1.0f / 3.0f));
        a2x += t2x * m4; a2y += t2y * m4; a2z += t2z * m4;
    }

    const float sc = 0.316227766017f;  // 1/sqrt(10)
    size_t base = (size_t)n * 1408;
    out[base + c]        = as0 * sc;
    out[base + 128 + c]  = as1 * sc;
    size_t vb = base + 256;
    out[vb + 3 * (size_t)c + 0] = a0x * sc;
    out[vb + 3 * (size_t)c + 1] = a0y * sc;
    out[vb + 3 * (size_t)c + 2] = a0z * sc;
    out[vb + 3 * (size_t)(128 + c) + 0] = a1x * sc;
    out[vb + 3 * (size_t)(128 + c) + 1] = a1y * sc;
    out[vb + 3 * (size_t)(128 + c) + 2] = a1z * sc;
    out[vb + 3 * (size_t)(256 + c) + 0] = a2x * sc;
    out[vb + 3 * (size_t)(256 + c) + 1] = a2y * sc;
    out[vb + 3 * (size_t)(256 + c) + 2] = a2z * sc;
}

// ---------------------------------------------------------------------------
extern "C" void kernel_launch(void* const* d_in, const int* in_sizes, int n_in,
                              void* d_out, int out_size) {
    const float* vectors   = (const float*)d_in[0];
    const float* node_feat = (const float*)d_in[1];
    const float* radial    = (const float*)d_in[2];
    const float* w0        = (const float*)d_in[3];
    const float* w1        = (const float*)d_in[4];
    const float* w2        = (const float*)d_in[5];
    const float* w3        = (const float*)d_in[6];
    const int*   senders   = (const int*)d_in[7];
    const int*   receivers = (const int*)d_in[8];
    float* out = (float*)d_out;

    int E = in_sizes[0] / 3;
    int N = in_sizes[1] / 512;

    convert_weights_kernel<<<(40960 + 255) / 256, 256>>>(w0, w1, w2, w3);

    const int SMEM_BYTES = 83200;
    cudaFuncSetAttribute(mlp_gemm_kernel,
                         cudaFuncAttributeMaxDynamicSharedMemorySize, SMEM_BYTES);
    mlp_gemm_kernel<<<(E + M_TILE - 1) / M_TILE, 256, SMEM_BYTES>>>(radial, E);

    zero_deg_kernel<<<(N + 255) / 256, 256>>>(N);
    hist_kernel<<<(E + 255) / 256, 256>>>(receivers, E);
    scan_kernel<<<1, 1024>>>(N, E);
    scatter_kernel<<<(E + 255) / 256, 256>>>(receivers, senders, E);

    gather_kernel<<<N, 128>>>(vectors, node_feat, out);
}

// round 12
// speedup vs baseline: 2.3044x; 1.3634x over previous
#include <cuda_runtime.h>
#include <cuda_fp16.h>
#include <mma.h>
#include <math.h>

using namespace nvcuda;

#define E_CAP 100096
#define N_CAP 10240
#define C 128
#define M_TILE 128

// Scratch (device globals: allocation rules forbid cudaMalloc)
__device__ __half g_MIX[(size_t)E_CAP * 640];   // receiver-CSR-ordered rows
__device__ __half g_w0h[512];
__device__ __half g_w1h[4096];
__device__ __half g_w2h[4096];
__device__ __half g_w3h[40960];
__device__ int    g_deg[N_CAP];
__device__ int    g_off[N_CAP + 1];
__device__ int    g_cur[N_CAP];
__device__ int    g_pos[E_CAP];                 // edge -> CSR slot
__device__ int    g_snd[E_CAP];                 // CSR-ordered senders
__device__ float4 g_rv[E_CAP];                  // CSR-ordered normalized r_hat

__device__ __forceinline__ float silu(float x) {
    return x / (1.0f + expf(-x));
}

// ---------------------------------------------------------------------------
// Convert weights fp32 -> fp16 (once per call; tiny)
// ---------------------------------------------------------------------------
__global__ void convert_weights_kernel(const float* __restrict__ w0,
                                       const float* __restrict__ w1,
                                       const float* __restrict__ w2,
                                       const float* __restrict__ w3) {
    int i = blockIdx.x * blockDim.x + threadIdx.x;
    if (i < 512)   g_w0h[i] = __float2half(w0[i]);
    if (i < 4096)  { g_w1h[i] = __float2half(w1[i]); g_w2h[i] = __float2half(w2[i]); }
    if (i < 40960) g_w3h[i] = __float2half(w3[i]);
}

// ---------------------------------------------------------------------------
// CSR-by-receiver build
// ---------------------------------------------------------------------------
__global__ void zero_deg_kernel(int N) {
    int i = blockIdx.x * blockDim.x + threadIdx.x;
    if (i < N) g_deg[i] = 0;
}

__global__ void hist_kernel(const int* __restrict__ recv, int E) {
    int i = blockIdx.x * blockDim.x + threadIdx.x;
    if (i < E) atomicAdd(&g_deg[recv[i]], 1);
}

// 1024-thread block, warp-shuffle two-level scan (2 barriers)
__global__ void scan_kernel(int N, int E) {
    __shared__ int warp_sums[32];
    int t = threadIdx.x;
    int lane = t & 31;
    int wid = t >> 5;
    int chunk = (N + 1023) / 1024;
    int lo = t * chunk;
    int hi = min(lo + chunk, N);

    int sum = 0;
    for (int i = lo; i < hi; i++) sum += g_deg[i];

    // inclusive warp scan
    int v = sum;
    #pragma unroll
    for (int d = 1; d < 32; d <<= 1) {
        int u = __shfl_up_sync(0xffffffffu, v, d);
        if (lane >= d) v += u;
    }
    if (lane == 31) warp_sums[wid] = v;
    __syncthreads();

    if (wid == 0) {
        int w = warp_sums[lane];
        #pragma unroll
        for (int d = 1; d < 32; d <<= 1) {
            int u = __shfl_up_sync(0xffffffffu, w, d);
            if (lane >= d) w += u;
        }
        warp_sums[lane] = w;
    }
    __syncthreads();

    int run = ((wid > 0) ? warp_sums[wid - 1] : 0) + (v - sum); // exclusive prefix
    for (int i = lo; i < hi; i++) {
        g_off[i] = run;
        g_cur[i] = run;
        run += g_deg[i];
    }
    if (t == 0) g_off[N] = E;
}

// scatter: assign CSR slots; record pos[e], reordered senders, normalized r_hat
__global__ void scatter_kernel(const int* __restrict__ recv,
                               const int* __restrict__ send,
                               const float* __restrict__ vectors, int E) {
    int i = blockIdx.x * blockDim.x + threadIdx.x;
    if (i < E) {
        int p = atomicAdd(&g_cur[recv[i]], 1);
        g_pos[i] = p;
        g_snd[p] = send[i];
        float vx = vectors[3 * (size_t)i + 0];
        float vy = vectors[3 * (size_t)i + 1];
        float vz = vectors[3 * (size_t)i + 2];
        float inv = rsqrtf(vx * vx + vy * vy + vz * vz);
        g_rv[p] = make_float4(vx * inv, vy * inv, vz * inv, 0.f);
    }
}

// ---------------------------------------------------------------------------
// Fused fp16-tensor-core kernel; MIX rows written to CSR slots (g_pos).
// ---------------------------------------------------------------------------
__global__ __launch_bounds__(256) void mlp_gemm_kernel(
        const float* __restrict__ re, int E) {
    extern __shared__ char smem_raw[];
    __half* sW0 = (__half*)smem_raw;       // 16 x 72 (rows 8..15 zero)
    __half* sW1 = sW0 + 16 * 72;           // 64 x 72
    __half* sW2 = sW1 + 64 * 72;           // 64 x 72
    __half* sH  = sW2 + 64 * 72;           // 128 x 72
    __half* sB  = sH + 128 * 72;           // 64 x 72
    float*  stg = (float*)(sB + 64 * 72);  // 8 warps x 16 x 68 floats

    int tid = threadIdx.x;
    int warp = tid >> 5;
    int lane = tid & 31;
    int m0 = blockIdx.x * M_TILE;
    int mrow = warp * 16;
    float* mystg = stg + warp * (16 * 68);

    // weights into smem (pad regions zeroed)
    for (int i = tid; i < 16 * 72; i += 256) {
        int r = i / 72, c = i % 72;
        sW0[i] = (r < 8 && c < 64) ? g_w0h[r * 64 + c] : __float2half(0.f);
    }
    for (int i = tid; i < 64 * 72; i += 256) {
        int r = i / 72, c = i % 72;
        __half z = __float2half(0.f);
        sW1[i] = (c < 64) ? g_w1h[r * 64 + c] : z;
        sW2[i] = (c < 64) ? g_w2h[r * 64 + c] : z;
    }
    for (int i = tid; i < 128 * 16; i += 256) {
        int r = i >> 4, c = i & 15;
        int e = m0 + r;
        float v = (e < E && c < 8) ? re[(size_t)e * 8 + c] : 0.f;
        sH[r * 72 + c] = __float2half(v);
    }
    __syncthreads();

    // per-warp CSR row slot for each of my 16 rows (lane r holds row r's slot)
    int myrow_e = m0 + mrow + lane;
    int prow = (lane < 16 && myrow_e < E) ? g_pos[myrow_e] : -1;

    typedef wmma::fragment<wmma::matrix_a, 16, 16, 16, __half, wmma::row_major> AFrag;
    typedef wmma::fragment<wmma::matrix_b, 16, 16, 16, __half, wmma::row_major> BFrag;
    typedef wmma::fragment<wmma::accumulator, 16, 16, 16, float> CFrag;

    CFrag acc[4];

    // ---------- layer 0 ----------
    {
        #pragma unroll
        for (int jj = 0; jj < 4; jj++) wmma::fill_fragment(acc[jj], 0.0f);
        AFrag a;
        wmma::load_matrix_sync(a, sH + mrow * 72, 72);
        #pragma unroll
        for (int jj = 0; jj < 4; jj++) {
            BFrag b;
            wmma::load_matrix_sync(b, sW0 + jj * 16, 72);
            wmma::mma_sync(acc[jj], a, b, acc[jj]);
        }
        #pragma unroll
        for (int jj = 0; jj < 4; jj++) {
            #pragma unroll
            for (int t = 0; t < acc[jj].num_elements; t++)
                acc[jj].x[t] = silu(acc[jj].x[t] * 0.35355339059f);
            wmma::store_matrix_sync(mystg + jj * 16, acc[jj], 68, wmma::mem_row_major);
        }
        __syncwarp();
        for (int idx = lane; idx < 16 * 64; idx += 32) {
            int r = idx >> 6, c = idx & 63;
            sH[(mrow + r) * 72 + c] = __float2half(mystg[r * 68 + c]);
        }
        __syncwarp();
    }

    // ---------- layers 1 & 2 ----------
    for (int layer = 0; layer < 2; layer++) {
        const __half* W = (layer == 0) ? sW1 : sW2;
        #pragma unroll
        for (int jj = 0; jj < 4; jj++) wmma::fill_fragment(acc[jj], 0.0f);
        #pragma unroll
        for (int k0 = 0; k0 < 64; k0 += 16) {
            AFrag a;
            wmma::load_matrix_sync(a, sH + mrow * 72 + k0, 72);
            #pragma unroll
            for (int jj = 0; jj < 4; jj++) {
                BFrag b;
                wmma::load_matrix_sync(b, W + k0 * 72 + jj * 16, 72);
                wmma::mma_sync(acc[jj], a, b, acc[jj]);
            }
        }
        #pragma unroll
        for (int jj = 0; jj < 4; jj++) {
            #pragma unroll
            for (int t = 0; t < acc[jj].num_elements; t++)
                acc[jj].x[t] = silu(acc[jj].x[t] * 0.125f);
            wmma::store_matrix_sync(mystg + jj * 16, acc[jj], 68, wmma::mem_row_major);
        }
        __syncwarp();
        for (int idx = lane; idx < 16 * 64; idx += 32) {
            int r = idx >> 6, c = idx & 63;
            sH[(mrow + r) * 72 + c] = __float2half(mystg[r * 68 + c]);
        }
        __syncwarp();
    }

    // ---------- main GEMM: [128x64] @ [64x640], 10 N-tiles ----------
    for (int nt = 0; nt < 10; nt++) {
        __syncthreads();
        for (int i = tid; i < 512; i += 256) {
            int k = i >> 3, q = i & 7;
            *(float4*)(sB + k * 72 + q * 8) =
                *(const float4*)(g_w3h + (size_t)k * 640 + nt * 64 + q * 8);
        }
        __syncthreads();

        #pragma unroll
        for (int jj = 0; jj < 4; jj++) wmma::fill_fragment(acc[jj], 0.0f);
        #pragma unroll
        for (int k0 = 0; k0 < 64; k0 += 16) {
            AFrag a;
            wmma::load_matrix_sync(a, sH + mrow * 72 + k0, 72);
            #pragma unroll
            for (int jj = 0; jj < 4; jj++) {
                BFrag b;
                wmma::load_matrix_sync(b, sB + k0 * 72 + jj * 16, 72);
                wmma::mma_sync(acc[jj], a, b, acc[jj]);
            }
        }

        #pragma unroll
        for (int jj = 0; jj < 4; jj++) {
            #pragma unroll
            for (int t = 0; t < acc[jj].num_elements; t++) acc[jj].x[t] *= 0.125f;
            wmma::store_matrix_sync(mystg + jj * 16, acc[jj], 68, wmma::mem_row_major);
        }
        __syncwarp();
        // half2 stores to g_MIX at CSR slot rows
        for (int idx = lane; idx < 16 * 32; idx += 32) {
            int r = idx >> 5, c2 = idx & 31;
            int pr = __shfl_sync(0xffffffffu, prow, r);
            if (pr >= 0) {
                __half2 h2 = __floats2half2_rn(mystg[r * 68 + c2 * 2],
                                               mystg[r * 68 + c2 * 2 + 1]);
                *(__half2*)(g_MIX + (size_t)pr * 640 + nt * 64 + c2 * 2) = h2;
            }
        }
        __syncwarp();
    }
}

// ---------------------------------------------------------------------------
// Gather-reduce: all edge data CSR-ordered (sequential reads).
// block = node, thread = channel c (0..127).
// ---------------------------------------------------------------------------
__global__ void gather_kernel(const float* __restrict__ nf,
                              float* __restrict__ out) {
    int n = blockIdx.x;
    int c = threadIdx.x;
    int lo = g_off[n];
    int hi = g_off[n + 1];

    float as0 = 0.f, as1 = 0.f;
    float a0x = 0.f, a0y = 0.f, a0z = 0.f;
    float a1x = 0.f, a1y = 0.f, a1z = 0.f;
    float a2x = 0.f, a2y = 0.f, a2z = 0.f;

    const float SQ3 = 1.73205080757f;

    #pragma unroll 2
    for (int k = lo; k < hi; k++) {
        int s = g_snd[k];
        float4 rv = g_rv[k];
        float rx = rv.x, ry = rv.y, rz = rv.z;

        const __half* mix = g_MIX + (size_t)k * 640;
        float m0 = __half2float(mix[c]);
        float m1 = __half2float(mix[128 + c]);
        float m2 = __half2float(mix[256 + c]);
        float m3 = __half2float(mix[384 + c]);
        float m4 = __half2float(mix[512 + c]);

        const float* nfr = nf + (size_t)s * 512;
        float ss = nfr[c];
        float v0 = nfr[128 + 3 * c + 0];
        float v1 = nfr[128 + 3 * c + 1];
        float v2 = nfr[128 + 3 * c + 2];

        float dot = v0 * rx + v1 * ry + v2 * rz;

        as0 += ss * m0;
        as1 += dot * m1;

        a0x += v0 * m2; a0y += v1 * m2; a0z += v2 * m2;
        a1x += ss * rx * m3; a1y += ss * ry * m3; a1z += ss * rz * m3;

        float t2x = SQ3 * (rx * dot - v0 * (1.0f / 3.0f));
        float t2y = SQ3 * (ry * dot - v1 * (1.0f / 3.0f));
        float t2z = SQ3 * (rz * dot - v2 * (1.0f / 3.0f));
        a2x += t2x * m4; a2y += t2y * m4; a2z += t2z * m4;
    }

    const float sc = 0.316227766017f;  // 1/sqrt(10)
    size_t base = (size_t)n * 1408;
    out[base + c]        = as0 * sc;
    out[base + 128 + c]  = as1 * sc;
    size_t vb = base + 256;
    out[vb + 3 * (size_t)c + 0] = a0x * sc;
    out[vb + 3 * (size_t)c + 1] = a0y * sc;
    out[vb + 3 * (size_t)c + 2] = a0z * sc;
    out[vb + 3 * (size_t)(128 + c) + 0] = a1x * sc;
    out[vb + 3 * (size_t)(128 + c) + 1] = a1y * sc;
    out[vb + 3 * (size_t)(128 + c) + 2] = a1z * sc;
    out[vb + 3 * (size_t)(256 + c) + 0] = a2x * sc;
    out[vb + 3 * (size_t)(256 + c) + 1] = a2y * sc;
    out[vb + 3 * (size_t)(256 + c) + 2] = a2z * sc;
}

// ---------------------------------------------------------------------------
extern "C" void kernel_launch(void* const* d_in, const int* in_sizes, int n_in,
                              void* d_out, int out_size) {
    const float* vectors   = (const float*)d_in[0];
    const float* node_feat = (const float*)d_in[1];
    const float* radial    = (const float*)d_in[2];
    const float* w0        = (const float*)d_in[3];
    const float* w1        = (const float*)d_in[4];
    const float* w2        = (const float*)d_in[5];
    const float* w3        = (const float*)d_in[6];
    const int*   senders   = (const int*)d_in[7];
    const int*   receivers = (const int*)d_in[8];
    float* out = (float*)d_out;

    int E = in_sizes[0] / 3;
    int N = in_sizes[1] / 512;

    convert_weights_kernel<<<(40960 + 255) / 256, 256>>>(w0, w1, w2, w3);

    // CSR build first (mlp_gemm needs g_pos)
    zero_deg_kernel<<<(N + 255) / 256, 256>>>(N);
    hist_kernel<<<(E + 255) / 256, 256>>>(receivers, E);
    scan_kernel<<<1, 1024>>>(N, E);
    scatter_kernel<<<(E + 255) / 256, 256>>>(receivers, senders, vectors, E);

    const int SMEM_BYTES = 83200;
    cudaFuncSetAttribute(mlp_gemm_kernel,
                         cudaFuncAttributeMaxDynamicSharedMemorySize, SMEM_BYTES);
    mlp_gemm_kernel<<<(E + M_TILE - 1) / M_TILE, 256, SMEM_BYTES>>>(radial, E);

    gather_kernel<<<N, 128>>>(node_feat, out);
}

// round 14
// speedup vs baseline: 2.3619x; 1.0249x over previous
#include <cuda_runtime.h>
#include <cuda_fp16.h>
#include <mma.h>
#include <math.h>

using namespace nvcuda;

#define E_CAP 100096
#define N_CAP 10240
#define C 128
#define M_TILE 256
#define THREADS 512

// Scratch (device globals: allocation rules forbid cudaMalloc)
__device__ __half g_MIX[(size_t)E_CAP * 640];   // receiver-CSR-ordered rows
__device__ __half g_w0h[512];
__device__ __half g_w1h[4096];
__device__ __half g_w2h[4096];
__device__ __half g_w3h[40960];                 // pre-scaled by 0.125
__device__ int    g_deg[N_CAP];
__device__ int    g_off[N_CAP + 1];
__device__ int    g_cur[N_CAP];
__device__ int    g_ord[E_CAP];                 // CSR slot -> edge id
__device__ int    g_snd[E_CAP];                 // CSR-ordered senders
__device__ float4 g_rv[E_CAP];                  // CSR-ordered normalized r_hat

__device__ __forceinline__ float silu(float x) {
    return x / (1.0f + expf(-x));
}

// ---------------------------------------------------------------------------
// Convert weights fp32 -> fp16 (0.125 GEMM scale folded into w3)
// ---------------------------------------------------------------------------
__global__ void convert_weights_kernel(const float* __restrict__ w0,
                                       const float* __restrict__ w1,
                                       const float* __restrict__ w2,
                                       const float* __restrict__ w3) {
    int i = blockIdx.x * blockDim.x + threadIdx.x;
    if (i < 512)   g_w0h[i] = __float2half(w0[i]);
    if (i < 4096)  { g_w1h[i] = __float2half(w1[i]); g_w2h[i] = __float2half(w2[i]); }
    if (i < 40960) g_w3h[i] = __float2half(w3[i] * 0.125f);
}

// ---------------------------------------------------------------------------
// CSR-by-receiver build
// ---------------------------------------------------------------------------
__global__ void hist_kernel(const int* __restrict__ recv, int E) {
    int i = blockIdx.x * blockDim.x + threadIdx.x;
    if (i < E) atomicAdd(&g_deg[recv[i]], 1);
}

__global__ void scan_kernel(int N, int E) {
    __shared__ int warp_sums[32];
    int t = threadIdx.x;
    int lane = t & 31;
    int wid = t >> 5;
    int chunk = (N + 1023) / 1024;
    int lo = t * chunk;
    int hi = min(lo + chunk, N);

    int sum = 0;
    #pragma unroll 4
    for (int i = lo; i < hi; i++) sum += g_deg[i];

    int v = sum;
    #pragma unroll
    for (int d = 1; d < 32; d <<= 1) {
        int u = __shfl_up_sync(0xffffffffu, v, d);
        if (lane >= d) v += u;
    }
    if (lane == 31) warp_sums[wid] = v;
    __syncthreads();

    if (wid == 0) {
        int w = warp_sums[lane];
        #pragma unroll
        for (int d = 1; d < 32; d <<= 1) {
            int u = __shfl_up_sync(0xffffffffu, w, d);
            if (lane >= d) w += u;
        }
        warp_sums[lane] = w;
    }
    __syncthreads();

    int run = ((wid > 0) ? warp_sums[wid - 1] : 0) + (v - sum);
    #pragma unroll 4
    for (int i = lo; i < hi; i++) {
        g_off[i] = run;
        g_cur[i] = run;
        run += g_deg[i];
    }
    if (t == 0) g_off[N] = E;
}

__global__ void scatter_kernel(const int* __restrict__ recv,
                               const int* __restrict__ send,
                               const float* __restrict__ vectors, int E) {
    int i = blockIdx.x * blockDim.x + threadIdx.x;
    if (i < E) {
        int p = atomicAdd(&g_cur[recv[i]], 1);
        g_ord[p] = i;
        g_snd[p] = send[i];
        float vx = vectors[3 * (size_t)i + 0];
        float vy = vectors[3 * (size_t)i + 1];
        float vz = vectors[3 * (size_t)i + 2];
        float inv = rsqrtf(vx * vx + vy * vy + vz * vz);
        g_rv[p] = make_float4(vx * inv, vy * inv, vz * inv, 0.f);
    }
}

// ---------------------------------------------------------------------------
// Fused fp16-tensor-core kernel. Rows = CSR slots (edges fetched via g_ord).
// 512 threads / 16 warps; w3 fully smem-resident; one block barrier total;
// A-fragments register-resident across all 10 N-tiles; direct half2 epilogue.
// ---------------------------------------------------------------------------
__global__ __launch_bounds__(THREADS) void mlp_gemm_kernel(
        const float* __restrict__ re, int E) {
    extern __shared__ char smem_raw[];
    __half* sW0 = (__half*)smem_raw;        // 16 x 72 (rows 8..15 zeroed)
    __half* sW1 = sW0 + 16 * 72;            // 64 x 72
    __half* sW2 = sW1 + 64 * 72;            // 64 x 72
    __half* sH  = sW2 + 64 * 72;            // 256 x 72
    __half* sW3 = sH + 256 * 72;            // 10 tiles x (64 x 72)
    float*  stgf = (float*)(sW3 + 10 * 64 * 72);  // 16 warps x 16 x 20 f32

    int tid = threadIdx.x;
    int warp = tid >> 5;
    int lane = tid & 31;
    int m0 = blockIdx.x * M_TILE;
    int mrow = warp * 16;
    float* mystg = stgf + warp * (16 * 20);

    // ---- cooperative loads ----
    // W0 (rows 8..15 zero; pad cols never read by frags but zero anyway)
    for (int i = tid; i < 16 * 72; i += THREADS) {
        int r = i / 72, c = i % 72;
        sW0[i] = (r < 8 && c < 64) ? g_w0h[r * 64 + c] : __float2half(0.f);
    }
    // W1 / W2 (pad cols 64..71 never read by 16-col frag loads)
    for (int i = tid; i < 64 * 64; i += THREADS) {
        int r = i >> 6, c = i & 63;
        sW1[r * 72 + c] = g_w1h[i];
        sW2[r * 72 + c] = g_w2h[i];
    }
    // W3: 10 tiles of 64x72 (vectorized 8-half chunks)
    for (int i = tid; i < 10 * 64 * 8; i += THREADS) {
        int nt = i >> 9;           // /512
        int rem = i & 511;
        int k = rem >> 3, q = rem & 7;
        *(float4*)(sW3 + nt * 4608 + k * 72 + q * 8) =
            *(const float4*)(g_w3h + (size_t)k * 640 + nt * 64 + q * 8);
    }
    // RE rows in CSR order: sH[r][0..7] = re[ord[m0+r]][0..7]; cols 8..15 = 0
    for (int i = tid; i < M_TILE * 8; i += THREADS) {
        int r = i >> 3, c = i & 7;
        int slot = m0 + r;
        float v = 0.f;
        if (slot < E) {
            int e = g_ord[slot];
            v = re[(size_t)e * 8 + c];
        }
        sH[r * 72 + c] = __float2half(v);
        sH[r * 72 + 8 + c] = __float2half(0.f);
    }
    __syncthreads();   // the only block barrier

    typedef wmma::fragment<wmma::matrix_a, 16, 16, 16, __half, wmma::row_major> AFrag;
    typedef wmma::fragment<wmma::matrix_b, 16, 16, 16, __half, wmma::row_major> BFrag;
    typedef wmma::fragment<wmma::accumulator, 16, 16, 16, float> CFrag;

    CFrag acc[4];

    // ---------- layer 0: [16x16(pad)] @ [16x64] ----------
    {
        #pragma unroll
        for (int jj = 0; jj < 4; jj++) wmma::fill_fragment(acc[jj], 0.0f);
        AFrag a;
        wmma::load_matrix_sync(a, sH + mrow * 72, 72);
        #pragma unroll
        for (int jj = 0; jj < 4; jj++) {
            BFrag b;
            wmma::load_matrix_sync(b, sW0 + jj * 16, 72);
            wmma::mma_sync(acc[jj], a, b, acc[jj]);
        }
        #pragma unroll
        for (int jj = 0; jj < 4; jj++) {
            #pragma unroll
            for (int t = 0; t < acc[jj].num_elements; t++)
                acc[jj].x[t] = silu(acc[jj].x[t] * 0.35355339059f);
            wmma::store_matrix_sync(mystg, acc[jj], 20, wmma::mem_row_major);
            __syncwarp();
            for (int p = lane; p < 256; p += 32) {
                int r = p >> 4, c = p & 15;
                sH[(mrow + r) * 72 + jj * 16 + c] = __float2half(mystg[r * 20 + c]);
            }
            __syncwarp();
        }
    }

    // ---------- layers 1 & 2: [16x64] @ [64x64], per-warp ----------
    for (int layer = 0; layer < 2; layer++) {
        const __half* W = (layer == 0) ? sW1 : sW2;
        #pragma unroll
        for (int jj = 0; jj < 4; jj++) wmma::fill_fragment(acc[jj], 0.0f);
        #pragma unroll
        for (int k0 = 0; k0 < 64; k0 += 16) {
            AFrag a;
            wmma::load_matrix_sync(a, sH + mrow * 72 + k0, 72);
            #pragma unroll
            for (int jj = 0; jj < 4; jj++) {
                BFrag b;
                wmma::load_matrix_sync(b, W + k0 * 72 + jj * 16, 72);
                wmma::mma_sync(acc[jj], a, b, acc[jj]);
            }
        }
        #pragma unroll
        for (int jj = 0; jj < 4; jj++) {
            #pragma unroll
            for (int t = 0; t < acc[jj].num_elements; t++)
                acc[jj].x[t] = silu(acc[jj].x[t] * 0.125f);
            wmma::store_matrix_sync(mystg, acc[jj], 20, wmma::mem_row_major);
            __syncwarp();
            for (int p = lane; p < 256; p += 32) {
                int r = p >> 4, c = p & 15;
                sH[(mrow + r) * 72 + jj * 16 + c] = __float2half(mystg[r * 20 + c]);
            }
            __syncwarp();
        }
    }

    // ---------- main GEMM: A frags register-resident, 10 N-tiles ----------
    AFrag aM[4];
    #pragma unroll
    for (int k = 0; k < 4; k++)
        wmma::load_matrix_sync(aM[k], sH + mrow * 72 + k * 16, 72);

    bool full_tile = (m0 + mrow + 16 <= E);

    for (int nt = 0; nt < 10; nt++) {
        const __half* Bt = sW3 + nt * 4608;
        #pragma unroll
        for (int jj = 0; jj < 4; jj++) wmma::fill_fragment(acc[jj], 0.0f);
        #pragma unroll
        for (int k0 = 0; k0 < 4; k0++) {
            #pragma unroll
            for (int jj = 0; jj < 4; jj++) {
                BFrag b;
                wmma::load_matrix_sync(b, Bt + k0 * 16 * 72 + jj * 16, 72);
                wmma::mma_sync(acc[jj], aM[k0], b, acc[jj]);
            }
        }
        // epilogue: stage f32 per-warp, emit half2 (scale already in w3)
        #pragma unroll
        for (int jj = 0; jj < 4; jj++) {
            wmma::store_matrix_sync(mystg, acc[jj], 20, wmma::mem_row_major);
            __syncwarp();
            if (full_tile) {
                #pragma unroll
                for (int t = 0; t < 4; t++) {
                    int p = lane + t * 32;      // 128 half2 slots
                    int r = p >> 3, c2 = p & 7;
                    __half2 h2 = __floats2half2_rn(mystg[r * 20 + c2 * 2],
                                                   mystg[r * 20 + c2 * 2 + 1]);
                    *(__half2*)(g_MIX + (size_t)(m0 + mrow + r) * 640
                                + nt * 64 + jj * 16 + c2 * 2) = h2;
                }
            } else {
                #pragma unroll
                for (int t = 0; t < 4; t++) {
                    int p = lane + t * 32;
                    int r = p >> 3, c2 = p & 7;
                    int row_e = m0 + mrow + r;
                    if (row_e < E) {
                        __half2 h2 = __floats2half2_rn(mystg[r * 20 + c2 * 2],
                                                       mystg[r * 20 + c2 * 2 + 1]);
                        *(__half2*)(g_MIX + (size_t)row_e * 640
                                    + nt * 64 + jj * 16 + c2 * 2) = h2;
                    }
                }
            }
            __syncwarp();
        }
    }
}

// ---------------------------------------------------------------------------
// Gather-reduce: all edge data CSR-ordered (sequential reads).
// ---------------------------------------------------------------------------
__global__ void gather_kernel(const float* __restrict__ nf,
                              float* __restrict__ out) {
    int n = blockIdx.x;
    int c = threadIdx.x;
    int lo = g_off[n];
    int hi = g_off[n + 1];

    float as0 = 0.f, as1 = 0.f;
    float a0x = 0.f, a0y = 0.f, a0z = 0.f;
    float a1x = 0.f, a1y = 0.f, a1z = 0.f;
    float a2x = 0.f, a2y = 0.f, a2z = 0.f;

    const float SQ3 = 1.73205080757f;

    #pragma unroll 2
    for (int k = lo; k < hi; k++) {
        int s = g_snd[k];
        float4 rv = g_rv[k];
        float rx = rv.x, ry = rv.y, rz = rv.z;

        const __half* mix = g_MIX + (size_t)k * 640;
        float m0 = __half2float(mix[c]);
        float m1 = __half2float(mix[128 + c]);
        float m2 = __half2float(mix[256 + c]);
        float m3 = __half2float(mix[384 + c]);
        float m4 = __half2float(mix[512 + c]);

        const float* nfr = nf + (size_t)s * 512;
        float ss = nfr[c];
        float v0 = nfr[128 + 3 * c + 0];
        float v1 = nfr[128 + 3 * c + 1];
        float v2 = nfr[128 + 3 * c + 2];

        float dot = v0 * rx + v1 * ry + v2 * rz;

        as0 += ss * m0;
        as1 += dot * m1;

        a0x += v0 * m2; a0y += v1 * m2; a0z += v2 * m2;
        a1x += ss * rx * m3; a1y += ss * ry * m3; a1z += ss * rz * m3;

        float t2x = SQ3 * (rx * dot - v0 * (1.0f / 3.0f));
        float t2y = SQ3 * (ry * dot - v1 * (1.0f / 3.0f));
        float t2z = SQ3 * (rz * dot - v2 * (1.0f / 3.0f));
        a2x += t2x * m4; a2y += t2y * m4; a2z += t2z * m4;
    }

    const float sc = 0.316227766017f;  // 1/sqrt(10)
    size_t base = (size_t)n * 1408;
    out[base + c]        = as0 * sc;
    out[base + 128 + c]  = as1 * sc;
    size_t vb = base + 256;
    out[vb + 3 * (size_t)c + 0] = a0x * sc;
    out[vb + 3 * (size_t)c + 1] = a0y * sc;
    out[vb + 3 * (size_t)c + 2] = a0z * sc;
    out[vb + 3 * (size_t)(128 + c) + 0] = a1x * sc;
    out[vb + 3 * (size_t)(128 + c) + 1] = a1y * sc;
    out[vb + 3 * (size_t)(128 + c) + 2] = a1z * sc;
    out[vb + 3 * (size_t)(256 + c) + 0] = a2x * sc;
    out[vb + 3 * (size_t)(256 + c) + 1] = a2y * sc;
    out[vb + 3 * (size_t)(256 + c) + 2] = a2z * sc;
}

// ---------------------------------------------------------------------------
extern "C" void kernel_launch(void* const* d_in, const int* in_sizes, int n_in,
                              void* d_out, int out_size) {
    const float* vectors   = (const float*)d_in[0];
    const float* node_feat = (const float*)d_in[1];
    const float* radial    = (const float*)d_in[2];
    const float* w0        = (const float*)d_in[3];
    const float* w1        = (const float*)d_in[4];
    const float* w2        = (const float*)d_in[5];
    const float* w3        = (const float*)d_in[6];
    const int*   senders   = (const int*)d_in[7];
    const int*   receivers = (const int*)d_in[8];
    float* out = (float*)d_out;

    int E = in_sizes[0] / 3;
    int N = in_sizes[1] / 512;

    convert_weights_kernel<<<(40960 + 255) / 256, 256>>>(w0, w1, w2, w3);

    void* deg_ptr = nullptr;
    cudaGetSymbolAddress(&deg_ptr, g_deg);
    cudaMemsetAsync(deg_ptr, 0, N * sizeof(int));

    hist_kernel<<<(E + 255) / 256, 256>>>(receivers, E);
    scan_kernel<<<1, 1024>>>(N, E);
    scatter_kernel<<<(E + 255) / 256, 256>>>(receivers, senders, vectors, E);

    // smem: halfs (1152+4608+4608+18432+46080)*2 = 149760 B + f32 stg 20480 B
    const int SMEM_BYTES = 149760 + 20480;   // 170240
    cudaFuncSetAttribute(mlp_gemm_kernel,
                         cudaFuncAttributeMaxDynamicSharedMemorySize, SMEM_BYTES);
    mlp_gemm_kernel<<<(E + M_TILE - 1) / M_TILE, THREADS, SMEM_BYTES>>>(radial, E);

    gather_kernel<<<N, 128>>>(node_feat, out);
}